// round 9
// baseline (speedup 1.0000x reference)
#include <cuda_runtime.h>
#include <cuda_bf16.h>

#define BS 2
#define NN 512
#define DD 128
#define JS 8            // j-splits in main GEMM
#define SZ (BS*NN*DD)   // 131072

typedef unsigned long long u64;

// ---------------- device scratch (no allocs allowed) ----------------
__device__ float g_sq[SZ];          // sigmoid(q)
__device__ float g_ek[SZ];          // exp(k)   (|k| <~ 5, safe unshifted)
__device__ float g_v [SZ];          // raw v
__device__ u64   g_eBd[NN*NN];      // exp(B) duplicated as (e,e) u64 pairs
__device__ float g_pn[JS*SZ];       // partial numerators
__device__ float g_pd[JS*SZ];       // partial denominators

// ---------------- f32x2 + cp.async helpers ----------------
__device__ __forceinline__ u64 pack2(float lo, float hi) {
    u64 r; asm("mov.b64 %0, {%1, %2};" : "=l"(r) : "f"(lo), "f"(hi)); return r;
}
__device__ __forceinline__ void ffma2(u64 &acc, u64 a, u64 b) {
    asm("fma.rn.f32x2 %0, %1, %2, %0;" : "+l"(acc) : "l"(a), "l"(b));
}
__device__ __forceinline__ u64 mul2(u64 a, u64 b) {
    u64 r; asm("mul.rn.f32x2 %0, %1, %2;" : "=l"(r) : "l"(a), "l"(b)); return r;
}
__device__ __forceinline__ float2 unpack2(u64 v) {
    float lo, hi; asm("mov.b64 {%0, %1}, %2;" : "=f"(lo), "=f"(hi) : "l"(v));
    return make_float2(lo, hi);
}
__device__ __forceinline__ void cp16(void* sdst, const void* gsrc) {
    unsigned s = (unsigned)__cvta_generic_to_shared(sdst);
    asm volatile("cp.async.ca.shared.global [%0], [%1], 16;" :: "r"(s), "l"(gsrc));
}
__device__ __forceinline__ void cp_commit() { asm volatile("cp.async.commit_group;"); }
template<int NPEND> __device__ __forceinline__ void cp_wait() {
    asm volatile("cp.async.wait_group %0;" :: "n"(NPEND));
}

// ---------------- K1: q/k/v projections (d-split) + eB dup ----------------
// grid (64, 7), 256 threads.
//   y = 0..5: GEMM slice: mat = y>>1 (0=q,1=k,2=v), d-half = y&1.
//             CTA tile: 16 rows x 64 cols. Thread: 2 rows x 2 cols (1 ffma2 x 2).
//   y = 6:    g_eBd = dup(exp(B)) elementwise.
__global__ __launch_bounds__(256) void proj_kernel(
    const float* __restrict__ x,
    const float* __restrict__ Wq, const float* __restrict__ bq,
    const float* __restrict__ Wk, const float* __restrict__ bk,
    const float* __restrict__ Wv, const float* __restrict__ bv,
    const float* __restrict__ Bm)
{
    __shared__ u64   xdup[16][128];    // (x,x) pairs, 16KB
    __shared__ float Ws[2][32][64];    // W chunk, d-half, 16KB
    const int slice = blockIdx.y;
    const int tid = threadIdx.x;

    if (slice == 6) {
        #pragma unroll
        for (int r = 0; r < 4; ++r) {
            const int off = blockIdx.x * 4096 + r * 1024 + tid * 4;
            const float4 b4 = *(const float4*)&Bm[off];
            u64* dst = &g_eBd[off];
            dst[0] = pack2(__expf(b4.x), __expf(b4.x));
            dst[1] = pack2(__expf(b4.y), __expf(b4.y));
            dst[2] = pack2(__expf(b4.z), __expf(b4.z));
            dst[3] = pack2(__expf(b4.w), __expf(b4.w));
        }
        return;
    }

    const int mat = slice >> 1;
    const int d0  = (slice & 1) * 64;
    const float* W    = (mat==0) ? Wq : ((mat==1) ? Wk : Wv);
    const float* bias = (mat==0) ? bq : ((mat==1) ? bk : bv);
    const int row0 = blockIdx.x * 16;
    const int dt = tid & 31, rt = tid >> 5;   // rt 0..7
    const int d = dt * 2;                     // column pair within the 64-half

    // stage x tile pre-duplicated (plain LDG + STS; visible after first barrier)
    #pragma unroll
    for (int t = 0; t < 2; ++t) {
        const int e = tid * 8 + t * 4;
        const int r = e >> 7, c = e & 127;
        const float4 xv = *(const float4*)&x[(row0 + r)*128 + c];
        u64* dst = &xdup[r][c];
        dst[0] = pack2(xv.x, xv.x); dst[1] = pack2(xv.y, xv.y);
        dst[2] = pack2(xv.z, xv.z); dst[3] = pack2(xv.w, xv.w);
    }
    // stage W chunk 0 (rows 0..31 of the d-half)
    #pragma unroll
    for (int q = 0; q < 2; ++q) {
        const int e = tid + q * 256;
        const int row = e >> 4, seg = (e & 15) * 4;
        cp16(&Ws[0][row][seg], &W[row*128 + d0 + seg]);
    }
    cp_commit();

    const float2 bb = *(const float2*)&bias[d0 + d];
    u64 a0 = pack2(bb.x, bb.y);
    u64 a1 = a0;

    for (int cc = 0; cc < 128; cc += 32) {
        const int s = (cc >> 5) & 1;
        if (cc + 32 < 128) {
            const int sn = s ^ 1;
            #pragma unroll
            for (int q = 0; q < 2; ++q) {
                const int e = tid + q * 256;
                const int row = e >> 4, seg = (e & 15) * 4;
                cp16(&Ws[sn][row][seg], &W[(cc + 32 + row)*128 + d0 + seg]);
            }
            cp_commit();
            cp_wait<1>();
        } else {
            cp_wait<0>();
        }
        __syncthreads();
        #pragma unroll
        for (int c = 0; c < 32; ++c) {
            const u64 w01 = ((const u64*)Ws[s][c])[dt];
            const u64 X0 = xdup[rt][cc + c];
            const u64 X1 = xdup[rt + 8][cc + c];
            ffma2(a0, X0, w01);
            ffma2(a1, X1, w01);
        }
        __syncthreads();
    }

    #pragma unroll
    for (int r = 0; r < 2; ++r) {
        const int grow = row0 + ((r == 0) ? rt : (rt + 8));
        float2 o = unpack2(r ? a1 : a0);
        const int off = grow*128 + d0 + d;
        if (mat == 0) {
            o.x = 1.f/(1.f+__expf(-o.x)); o.y = 1.f/(1.f+__expf(-o.y));
            *(float2*)&g_sq[off] = o;
        } else if (mat == 1) {
            o.x = __expf(o.x); o.y = __expf(o.y);
            *(float2*)&g_ek[off] = o;
        } else {
            *(float2*)&g_v[off] = o;
        }
    }
}

// ---------------- K2: partial GEMM  pn|pd += eB @ (ek*v | ek) ----------------
// grid (128, 2, 2): x = itile(16)*js(8), y = 64-d half, z = batch. 128 threads.
// CTA tile: 32 i x 64 d x 64 j. Thread tile: 4 i x 4 d, 16 f32x2 accumulators.
// eB comes pre-duplicated (u64), ev = ek*v on the fly.
__global__ __launch_bounds__(128) void aft_kernel()
{
    __shared__ u64   eBs[2][32][36];   // [i][j] dup pairs, padded (288B rows)
    __shared__ float vvs[2][32][64];   // raw v
    __shared__ float eks[2][32][64];   // exp(k)
    const int jx  = blockIdx.x & 7;
    const int it0 = (blockIdx.x >> 3) * 32;
    const int jb  = jx * 64;
    const int d0  = blockIdx.y * 64;
    const int b   = blockIdx.z;
    const int tid = threadIdx.x;
    const int dt = tid & 15, rt = tid >> 4;
    const int d = dt * 4;
    const int i0 = rt * 4;
    const float* vb  = g_v  + b*NN*DD + d0;
    const float* ekb = g_ek + b*NN*DD + d0;

    u64 aN[4][2], aD[4][2];
    #pragma unroll
    for (int ii = 0; ii < 4; ++ii) {
        aN[ii][0] = 0; aN[ii][1] = 0; aD[ii][0] = 0; aD[ii][1] = 0;
    }

    auto stage = [&](int s, int jc) {
        #pragma unroll
        for (int q = 0; q < 4; ++q) {
            const int e = tid + q*128;
            const int j = e >> 4, dd = (e & 15) * 4;
            cp16(&vvs[s][j][dd], &vb[(jb + jc + j)*DD + dd]);
            cp16(&eks[s][j][dd], &ekb[(jb + jc + j)*DD + dd]);
        }
        // eB dup: 32 i x 32 j u64 = 512 cp16 pairs / 128 thr = 4 each
        #pragma unroll
        for (int q = 0; q < 4; ++q) {
            const int e = tid + q*128;
            const int ri = e >> 4, c2 = (e & 15) * 2;
            cp16(&eBs[s][ri][c2], &g_eBd[(it0 + ri)*NN + jb + jc + c2]);
        }
    };

    stage(0, 0);
    cp_commit();

    for (int m = 0; m < 2; ++m) {
        const int s = m & 1;
        if (m + 1 < 2) { stage(s ^ 1, 32); cp_commit(); cp_wait<1>(); }
        else           { cp_wait<0>(); }
        __syncthreads();
        #pragma unroll 8
        for (int j = 0; j < 32; ++j) {
            const u64* vp = (const u64*)&vvs[s][j][d];
            const u64* kp = (const u64*)&eks[s][j][d];
            const u64 v01 = vp[0], v23 = vp[1], k01 = kp[0], k23 = kp[1];
            const u64 ev01 = mul2(k01, v01), ev23 = mul2(k23, v23);
            #pragma unroll
            for (int ii = 0; ii < 4; ++ii) {
                const u64 E = eBs[s][i0 + ii][j];
                ffma2(aN[ii][0], E, ev01); ffma2(aN[ii][1], E, ev23);
                ffma2(aD[ii][0], E, k01);  ffma2(aD[ii][1], E, k23);
            }
        }
        __syncthreads();
    }

    const int pbase = jx * SZ;
    #pragma unroll
    for (int ii = 0; ii < 4; ++ii) {
        const int gi = it0 + i0 + ii;
        const int off = (b*NN + gi)*DD + d0 + d;
        const float2 n01 = unpack2(aN[ii][0]), n23 = unpack2(aN[ii][1]);
        const float2 q01 = unpack2(aD[ii][0]), q23 = unpack2(aD[ii][1]);
        *(float4*)&g_pn[pbase + off] = make_float4(n01.x, n01.y, n23.x, n23.y);
        *(float4*)&g_pd[pbase + off] = make_float4(q01.x, q01.y, q23.x, q23.y);
    }
}

// ---------------- K3: reduce partials + epilogue ----------------
__global__ __launch_bounds__(256) void reduce_kernel(float* __restrict__ out)
{
    const int off = (blockIdx.x * 256 + threadIdx.x) * 4;
    float4 n = *(const float4*)&g_pn[off];
    float4 dn = *(const float4*)&g_pd[off];
    #pragma unroll
    for (int js = 1; js < JS; ++js) {
        const float4 a = *(const float4*)&g_pn[js*SZ + off];
        const float4 c = *(const float4*)&g_pd[js*SZ + off];
        n.x += a.x; n.y += a.y; n.z += a.z; n.w += a.w;
        dn.x += c.x; dn.y += c.y; dn.z += c.z; dn.w += c.w;
    }
    const float4 sq = *(const float4*)&g_sq[off];
    float4 o;
    o.x = sq.x * __fdividef(n.x, dn.x);
    o.y = sq.y * __fdividef(n.y, dn.y);
    o.z = sq.z * __fdividef(n.z, dn.z);
    o.w = sq.w * __fdividef(n.w, dn.w);
    *(float4*)&out[off] = o;
}

// ---------------- launch ----------------
extern "C" void kernel_launch(void* const* d_in, const int* in_sizes, int n_in,
                              void* d_out, int out_size)
{
    const float* x  = (const float*)d_in[0];
    const float* Wq = (const float*)d_in[1];
    const float* bq = (const float*)d_in[2];
    const float* Wk = (const float*)d_in[3];
    const float* bk = (const float*)d_in[4];
    const float* Wv = (const float*)d_in[5];
    const float* bv = (const float*)d_in[6];
    const float* B  = (const float*)d_in[7];
    float* out = (float*)d_out;

    proj_kernel<<<dim3(64, 7), 256>>>(x, Wq, bq, Wk, bk, Wv, bv, B);
    aft_kernel<<<dim3(128, 2, 2), 128>>>();
    reduce_kernel<<<SZ/4/256, 256>>>(out);
}